// round 3
// baseline (speedup 1.0000x reference)
#include <cuda_runtime.h>
#include <cstdint>

// ============================================================
// LSTM_79216376807633: 2-layer LSTM (B=64, T=512, H=1024, in=128) + FC
// Single persistent kernel (software grid barrier), f32x2 packed FMA
// inner loop. Graph = 2 nodes total (persistent + FC) to avoid the
// multi-MB graph-exec upload buffer that a 1026-node graph leaves live.
// ============================================================

#define BATCH 64
#define HID   1024
#define TLEN  512
#define NCTA  128

// double-buffered hidden states + cell states (scratch via __device__ globals)
__device__ float g_h0[2][BATCH * HID];
__device__ float g_c0[BATCH * HID];
__device__ float g_h1[2][BATCH * HID];
__device__ float g_c1[BATCH * HID];

// software grid barrier state (self-resetting; valid across graph replays)
__device__ unsigned g_bar_count;
__device__ unsigned g_bar_gen;

__device__ __forceinline__ void grid_barrier() {
    __syncthreads();
    if (threadIdx.x == 0) {
        __threadfence();                         // publish my CTA's writes
        unsigned gen = *(volatile unsigned*)&g_bar_gen;
        if (atomicAdd(&g_bar_count, 1u) == NCTA - 1) {
            g_bar_count = 0;
            __threadfence();
            *(volatile unsigned*)&g_bar_gen = gen + 1;
        } else {
            while (*(volatile unsigned*)&g_bar_gen == gen) {}
            __threadfence();                     // acquire others' writes
        }
    }
    __syncthreads();
}

__device__ __forceinline__ unsigned long long pack2(float x) {
    unsigned long long r;
    asm("mov.b64 %0, {%1, %1};" : "=l"(r) : "f"(x));
    return r;
}
__device__ __forceinline__ void fma2(unsigned long long &d, unsigned long long a,
                                     unsigned long long b) {
    asm("fma.rn.f32x2 %0, %1, %2, %0;" : "+l"(d) : "l"(a), "l"(b));
}
__device__ __forceinline__ float2 unpack2(unsigned long long v) {
    float2 f;
    asm("mov.b64 {%0, %1}, %2;" : "=f"(f.x), "=f"(f.y) : "l"(v));
    return f;
}

// One LSTM timestep for one layer; this CTA handles h-dims [m0, m0+8).
// KX = input feature dim (128 for layer0, 1024 for layer1).
template <int KX>
__device__ __forceinline__ void
lstm_step(const float* __restrict__ xin, int xstride,
          const float* __restrict__ hprev,
          const float* __restrict__ Wih,   // [4096, KX]
          const float* __restrict__ Whh,   // [4096, HID]
          const float* __restrict__ bih,   // [4096]
          const float* __restrict__ bhh,   // [4096]
          float* __restrict__ cst,         // [64, HID] in-place (CTA-exclusive slice)
          float* __restrict__ hnext,       // [64, HID]
          float (&sa)[2][32][66],
          float (&sw)[2][32][36])
{
    constexpr int KTOT  = KX + HID;
    constexpr int KHALF = KTOT / 2;
    constexpr int NCH   = KHALF / 32;   // 32-wide K chunks per group

    const int tid = threadIdx.x;
    const int grp = tid >> 7;        // K-split group: 0 or 1
    const int u   = tid & 127;       // lane within group
    const int tb  = u >> 3;          // 0..15  -> batch quad
    const int tj  = u & 7;           // 0..7   -> gate-col quad
    const int b0  = tb * 4;
    const int jt  = tj * 4;          // tile-local j base (0..28)
    const int m0  = blockIdx.x * 8;  // h-dim base for this CTA

    // 16 outputs/thread: 4 gate-cols x 4 batches, f32x2 pairs over batch.
    unsigned long long acc[4][2] = {};

    float4 av[4];  // activation prefetch
    float4 wv[2];  // weight prefetch

    auto prefetch = [&](int ch) {
        const int kg = grp * KHALF + ch * 32;   // virtual K position (x part then h part)
        const float* ab; int ast; const float* wb; int wst; int ko;
        if (kg < KX) { ab = xin;   ast = xstride; wb = Wih; wst = KX;  ko = kg; }
        else         { ab = hprev; ast = HID;     wb = Whh; wst = HID; ko = kg - KX; }
#pragma unroll
        for (int r = 0; r < 4; r++) {
            int tau = u + 128 * r;
            int k4 = tau & 7, bb = tau >> 3;           // 64 b x 8 k4 tasks
            av[r] = *reinterpret_cast<const float4*>(ab + bb * ast + ko + k4 * 4);
        }
#pragma unroll
        for (int r = 0; r < 2; r++) {
            int tau = u + 128 * r;
            int k4 = tau & 7, jj = tau >> 3;           // 32 j x 8 k4 tasks
            int grow = (jj >> 3) * HID + m0 + (jj & 7);  // global gate row
            wv[r] = *reinterpret_cast<const float4*>(wb + grow * wst + ko + k4 * 4);
        }
    };

    auto store_smem = [&]() {
#pragma unroll
        for (int r = 0; r < 4; r++) {
            int tau = u + 128 * r;
            int k4 = tau & 7, bb = tau >> 3;
            sa[grp][k4 * 4 + 0][bb] = av[r].x;
            sa[grp][k4 * 4 + 1][bb] = av[r].y;
            sa[grp][k4 * 4 + 2][bb] = av[r].z;
            sa[grp][k4 * 4 + 3][bb] = av[r].w;
        }
#pragma unroll
        for (int r = 0; r < 2; r++) {
            int tau = u + 128 * r;
            int k4 = tau & 7, jj = tau >> 3;
            sw[grp][k4 * 4 + 0][jj] = wv[r].x;
            sw[grp][k4 * 4 + 1][jj] = wv[r].y;
            sw[grp][k4 * 4 + 2][jj] = wv[r].z;
            sw[grp][k4 * 4 + 3][jj] = wv[r].w;
        }
    };

    prefetch(0);
    for (int ch = 0; ch < NCH; ch++) {
        __syncthreads();   // prior chunk fully consumed (also guards smem reuse)
        store_smem();
        __syncthreads();
        if (ch + 1 < NCH) prefetch(ch + 1);  // LDG overlaps compute

#pragma unroll
        for (int kk = 0; kk < 32; kk++) {
            unsigned long long a01 =
                *reinterpret_cast<const unsigned long long*>(&sa[grp][kk][b0]);
            unsigned long long a23 =
                *reinterpret_cast<const unsigned long long*>(&sa[grp][kk][b0 + 2]);
            float4 w4 = *reinterpret_cast<const float4*>(&sw[grp][kk][jt]);
            unsigned long long wq;
            wq = pack2(w4.x); fma2(acc[0][0], a01, wq); fma2(acc[0][1], a23, wq);
            wq = pack2(w4.y); fma2(acc[1][0], a01, wq); fma2(acc[1][1], a23, wq);
            wq = pack2(w4.z); fma2(acc[2][0], a01, wq); fma2(acc[2][1], a23, wq);
            wq = pack2(w4.w); fma2(acc[3][0], a01, wq); fma2(acc[3][1], a23, wq);
        }
    }

    // ---- cross-group K reduction ----
    __syncthreads();
    unsigned long long* red = reinterpret_cast<unsigned long long*>(&sa[1][0][0]);
    if (grp == 1) {
#pragma unroll
        for (int q = 0; q < 4; q++)
#pragma unroll
            for (int p = 0; p < 2; p++)
                red[u * 8 + q * 2 + p] = acc[q][p];
    }
    __syncthreads();

    // ---- stage gate preacts (with bias) into smem as [j_tile][batch] ----
    float* gsh = &sa[0][0][0];   // 32 x 64 floats, fits in sa[0] region
    if (grp == 0) {
#pragma unroll
        for (int q = 0; q < 4; q++) {
            int j = jt + q;
            int grow = (j >> 3) * HID + m0 + (j & 7);
            float bias = bih[grow] + bhh[grow];
#pragma unroll
            for (int p = 0; p < 2; p++) {
                float2 mine = unpack2(acc[q][p]);
                float2 oth  = unpack2(red[u * 8 + q * 2 + p]);
                gsh[j * 64 + b0 + 2 * p + 0] = mine.x + oth.x + bias;
                gsh[j * 64 + b0 + 2 * p + 1] = mine.y + oth.y + bias;
            }
        }
    }
    __syncthreads();

    // ---- cell update: 512 cells (8 m x 64 b), 2 per thread ----
#pragma unroll
    for (int cid = tid; cid < 512; cid += 256) {
        int m = cid >> 6, b = cid & 63;
        float iv = gsh[(0 * 8 + m) * 64 + b];
        float fv = gsh[(1 * 8 + m) * 64 + b];
        float gv = gsh[(2 * 8 + m) * 64 + b];
        float ov = gsh[(3 * 8 + m) * 64 + b];
        float is = 1.0f / (1.0f + expf(-iv));
        float fs = 1.0f / (1.0f + expf(-fv));
        float gt = tanhf(gv);
        float os = 1.0f / (1.0f + expf(-ov));
        int idx = b * HID + m0 + m;
        float cn = fs * cst[idx] + is * gt;
        cst[idx] = cn;
        hnext[idx] = os * tanhf(cn);
    }
}

// Persistent kernel: init + full 512-step, 2-layer recurrence.
// One grid barrier per timestep:
//   L0(0); B; loop t: { L1(t); L0(t+1); B }
// Valid because L0(t+1) depends only on h0(t), published at the same
// barrier that L1(t) waits on; h1/c buffers are protected by the
// end-of-iteration barrier; c-slices are CTA-exclusive.
__global__ void __launch_bounds__(256, 1)
lstm_persistent_kernel(const float* __restrict__ x,
                       const float* __restrict__ Wih0, const float* __restrict__ Whh0,
                       const float* __restrict__ bih0, const float* __restrict__ bhh0,
                       const float* __restrict__ Wih1, const float* __restrict__ Whh1,
                       const float* __restrict__ bih1, const float* __restrict__ bhh1)
{
    __shared__ __align__(16) float sa[2][32][66];
    __shared__ __align__(16) float sw[2][32][36];

    // ---- zero my slice of all state buffers (512 elems each per CTA) ----
    {
        int base = blockIdx.x * 512;
        for (int i = threadIdx.x; i < 512; i += 256) {
            g_h0[0][base + i] = 0.0f; g_h0[1][base + i] = 0.0f;
            g_h1[0][base + i] = 0.0f; g_h1[1][base + i] = 0.0f;
            g_c0[base + i] = 0.0f;    g_c1[base + i] = 0.0f;
        }
    }
    grid_barrier();

    // L0 step t=0: hprev = h0 buf[0], next = buf[1]
    lstm_step<128>(x, TLEN * 128, g_h0[0], Wih0, Whh0, bih0, bhh0,
                   g_c0, g_h0[1], sa, sw);
    grid_barrier();

    for (int t = 0; t < TLEN; t++) {
        const float* h0cur = g_h0[(t + 1) & 1];          // h0(t)
        // layer1 step t
        lstm_step<1024>(h0cur, HID, g_h1[t & 1], Wih1, Whh1, bih1, bhh1,
                        g_c1, g_h1[(t + 1) & 1], sa, sw);
        // layer0 step t+1 (depends only on h0(t), already published)
        if (t + 1 < TLEN) {
            lstm_step<128>(x + (t + 1) * 128, TLEN * 128, h0cur,
                           Wih0, Whh0, bih0, bhh0, g_c0, g_h0[t & 1], sa, sw);
        }
        grid_barrier();
    }
    // final h1(T-1) lives in g_h1[TLEN & 1] == g_h1[0]
}

__global__ void lstm_fc_kernel(const float* __restrict__ h,
                               const float* __restrict__ w,
                               const float* __restrict__ bias,
                               float* __restrict__ out) {
    __shared__ float warpsum[8];
    int b = blockIdx.x, tid = threadIdx.x;
    float s = 0.0f;
    for (int m = tid; m < HID; m += 256) s += h[b * HID + m] * w[m];
#pragma unroll
    for (int o = 16; o; o >>= 1) s += __shfl_down_sync(0xffffffffu, s, o);
    if ((tid & 31) == 0) warpsum[tid >> 5] = s;
    __syncthreads();
    if (tid == 0) {
        float t = 0.0f;
#pragma unroll
        for (int i = 0; i < 8; i++) t += warpsum[i];
        out[b] = t + bias[0];
    }
}

extern "C" void kernel_launch(void* const* d_in, const int* in_sizes, int n_in,
                              void* d_out, int out_size) {
    const float* x    = (const float*)d_in[0];   // [64, 512, 128]
    const float* Wih0 = (const float*)d_in[1];   // [4096, 128]
    const float* Whh0 = (const float*)d_in[2];   // [4096, 1024]
    const float* bih0 = (const float*)d_in[3];
    const float* bhh0 = (const float*)d_in[4];
    const float* Wih1 = (const float*)d_in[5];   // [4096, 1024]
    const float* Whh1 = (const float*)d_in[6];   // [4096, 1024]
    const float* bih1 = (const float*)d_in[7];
    const float* bhh1 = (const float*)d_in[8];
    const float* fcw  = (const float*)d_in[9];   // [1, 1024]
    const float* fcb  = (const float*)d_in[10];  // [1]
    float* out = (float*)d_out;

    float* h1;
    cudaGetSymbolAddress((void**)&h1, g_h1);   // final h in first buffer

    lstm_persistent_kernel<<<NCTA, 256>>>(x, Wih0, Whh0, bih0, bhh0,
                                          Wih1, Whh1, bih1, bhh1);
    lstm_fc_kernel<<<64, 256>>>(h1, fcw, fcb, out);
}

// round 5
// speedup vs baseline: 1.3205x; 1.3205x over previous
#include <cuda_runtime.h>
#include <cstdint>

// ============================================================
// LSTM_79216376807633: 2-layer LSTM (B=64, T=512, H=1024, in=128) + FC
// Persistent kernel, 512 threads/CTA, 4-way K-split, XOR-swizzled
// conflict-free smem staging, f32x2 packed FMA inner loop.
// ============================================================

#define BATCH 64
#define HID   1024
#define TLEN  512
#define NCTA  128
#define NG    4

__device__ float g_h0[2][BATCH * HID];
__device__ float g_c0[BATCH * HID];
__device__ float g_h1[2][BATCH * HID];
__device__ float g_c1[BATCH * HID];

__device__ unsigned g_bar_count;
__device__ unsigned g_bar_gen;

__device__ __forceinline__ void grid_barrier() {
    __syncthreads();
    if (threadIdx.x == 0) {
        __threadfence();                         // publish my CTA's writes
        unsigned gen = *(volatile unsigned*)&g_bar_gen;
        if (atomicAdd(&g_bar_count, 1u) == NCTA - 1) {
            g_bar_count = 0;
            __threadfence();
            *(volatile unsigned*)&g_bar_gen = gen + 1;
        } else {
            while (*(volatile unsigned*)&g_bar_gen == gen) {}
            __threadfence();                     // acquire others' writes
        }
    }
    __syncthreads();
}

#define GROUP_BAR(g) \
    asm volatile("bar.sync %0, %1;" :: "r"((g) + 1), "r"(128) : "memory")

__device__ __forceinline__ unsigned long long pack2(float x) {
    unsigned long long r;
    asm("mov.b64 %0, {%1, %1};" : "=l"(r) : "f"(x));
    return r;
}
__device__ __forceinline__ void fma2(unsigned long long &d, unsigned long long a,
                                     unsigned long long b) {
    asm("fma.rn.f32x2 %0, %1, %2, %0;" : "+l"(d) : "l"(a), "l"(b));
}
__device__ __forceinline__ unsigned long long add2(unsigned long long a,
                                                   unsigned long long b) {
    unsigned long long r;
    asm("add.rn.f32x2 %0, %1, %2;" : "=l"(r) : "l"(a), "l"(b));
    return r;
}
__device__ __forceinline__ float2 unpack2(unsigned long long v) {
    float2 f;
    asm("mov.b64 {%0, %1}, %2;" : "=f"(f.x), "=f"(f.y) : "l"(v));
    return f;
}

// One LSTM timestep for one layer; this CTA handles h-dims [m0, m0+8).
// 512 threads = 4 K-groups x 128. Each group stages its private 32-wide
// K chunk into swizzled smem (conflict-free), accumulates 4j x 4b outputs
// per thread as f32x2 pairs, then a 4-way cross-group reduction + fused
// gate nonlinearity + cell update.
template <int KX>
__device__ __forceinline__ void
lstm_step(const float* __restrict__ xin, int xstride,
          const float* __restrict__ hprev,
          const float* __restrict__ Wih,   // [4096, KX]
          const float* __restrict__ Whh,   // [4096, HID]
          const float* __restrict__ bih,
          const float* __restrict__ bhh,
          float* __restrict__ cst,         // [64, HID] in-place (CTA-exclusive slice)
          float* __restrict__ hnext,       // [64, HID]
          float (&sa)[NG][32][64],
          float (&sw)[NG][32][32])
{
    constexpr int KTOT = KX + HID;
    constexpr int KQ   = KTOT / NG;      // K per group
    constexpr int NCH  = KQ / 32;        // 32-wide chunks per group

    const int tid = threadIdx.x;
    const int grp = tid >> 7;            // 0..3
    const int u   = tid & 127;
    const int b0  = (u >> 3) * 4;        // batch quad base (0..60)
    const int jt  = (u & 7) * 4;         // gate-col quad base (0..28)
    const int m0  = blockIdx.x * 8;

    unsigned long long acc[4][2] = {};   // [j][batch-pair]

    float4 av[4];                        // activation prefetch
    float4 wv[2];                        // weight prefetch

    auto prefetch = [&](int ch) {
        const int kg = grp * KQ + ch * 32;   // virtual K position (x part then h part)
        const float* ab; int ast; const float* wb; int wst; int ko;
        if (kg < KX) { ab = xin;   ast = xstride; wb = Wih; wst = KX;  ko = kg; }
        else         { ab = hprev; ast = HID;     wb = Whh; wst = HID; ko = kg - KX; }
#pragma unroll
        for (int r = 0; r < 4; r++) {
            int tau = u + 128 * r;
            int k4 = tau & 7, bb = tau >> 3;             // 64 b x 8 k4 tasks
            av[r] = *reinterpret_cast<const float4*>(ab + bb * ast + ko + k4 * 4);
        }
#pragma unroll
        for (int r = 0; r < 2; r++) {
            int tau = u + 128 * r;
            int k4 = tau & 7, jj = tau >> 3;             // 32 j x 8 k4 tasks
            int grow = (jj >> 3) * HID + m0 + (jj & 7);  // global gate row
            wv[r] = *reinterpret_cast<const float4*>(wb + grow * wst + ko + k4 * 4);
        }
    };

    // XOR-swizzled transpose store: col = idx ^ (k4<<2) -> conflict-free
    auto store_smem = [&]() {
#pragma unroll
        for (int r = 0; r < 4; r++) {
            int tau = u + 128 * r;
            int k4 = tau & 7, bb = tau >> 3;
            int col = bb ^ (k4 << 2);
            sa[grp][k4 * 4 + 0][col] = av[r].x;
            sa[grp][k4 * 4 + 1][col] = av[r].y;
            sa[grp][k4 * 4 + 2][col] = av[r].z;
            sa[grp][k4 * 4 + 3][col] = av[r].w;
        }
#pragma unroll
        for (int r = 0; r < 2; r++) {
            int tau = u + 128 * r;
            int k4 = tau & 7, jj = tau >> 3;
            int col = jj ^ (k4 << 2);
            sw[grp][k4 * 4 + 0][col] = wv[r].x;
            sw[grp][k4 * 4 + 1][col] = wv[r].y;
            sw[grp][k4 * 4 + 2][col] = wv[r].z;
            sw[grp][k4 * 4 + 3][col] = wv[r].w;
        }
    };

    prefetch(0);
    for (int ch = 0; ch < NCH; ch++) {
        GROUP_BAR(grp);                  // group's prior reads done
        store_smem();
        GROUP_BAR(grp);                  // group's stores visible
        if (ch + 1 < NCH) prefetch(ch + 1);

#pragma unroll
        for (int kk = 0; kk < 32; kk++) {
            const int xs = (kk >> 2) << 2;          // swizzle selector (compile-time)
            ulonglong2 a2 = *reinterpret_cast<const ulonglong2*>(
                &sa[grp][kk][b0 ^ xs]);
            float4 w4 = *reinterpret_cast<const float4*>(
                &sw[grp][kk][jt ^ xs]);
            unsigned long long wq;
            wq = pack2(w4.x); fma2(acc[0][0], a2.x, wq); fma2(acc[0][1], a2.y, wq);
            wq = pack2(w4.y); fma2(acc[1][0], a2.x, wq); fma2(acc[1][1], a2.y, wq);
            wq = pack2(w4.z); fma2(acc[2][0], a2.x, wq); fma2(acc[2][1], a2.y, wq);
            wq = pack2(w4.w); fma2(acc[3][0], a2.x, wq); fma2(acc[3][1], a2.y, wq);
        }
    }

    // ---- 4-way cross-group K reduction (groups 1..3 -> group 0) ----
    __syncthreads();
    unsigned long long* red = reinterpret_cast<unsigned long long*>(&sa[0][0][0]);
    if (grp != 0) {
        unsigned long long* dst = red + (grp - 1) * 1024 + u * 8;
#pragma unroll
        for (int q = 0; q < 4; q++)
#pragma unroll
            for (int p = 0; p < 2; p++)
                dst[q * 2 + p] = acc[q][p];
    }
    __syncthreads();

    // ---- group 0: reduce, add bias, stage gate preacts [j][batch] ----
    float* gsh = &sw[0][0][0];   // 2048 floats, fits in sw region
    if (grp == 0) {
#pragma unroll
        for (int q = 0; q < 4; q++) {
            int j = jt + q;                          // 0..31: gate = j>>3, m = j&7
            int grow = (j >> 3) * HID + m0 + (j & 7);
            float bias = bih[grow] + bhh[grow];
#pragma unroll
            for (int p = 0; p < 2; p++) {
                unsigned long long t = acc[q][p];
                t = add2(t, red[u * 8 + q * 2 + p]);
                t = add2(t, red[1024 + u * 8 + q * 2 + p]);
                t = add2(t, red[2048 + u * 8 + q * 2 + p]);
                float2 v = unpack2(t);
                gsh[j * 64 + b0 + 2 * p + 0] = v.x + bias;
                gsh[j * 64 + b0 + 2 * p + 1] = v.y + bias;
            }
        }
    }
    __syncthreads();

    // ---- cell update: 512 cells (8 m x 64 b), one per thread ----
    {
        int m = tid >> 6, b = tid & 63;
        float iv = gsh[(0 * 8 + m) * 64 + b];
        float fv = gsh[(1 * 8 + m) * 64 + b];
        float gv = gsh[(2 * 8 + m) * 64 + b];
        float ov = gsh[(3 * 8 + m) * 64 + b];
        float is = 1.0f / (1.0f + expf(-iv));
        float fs = 1.0f / (1.0f + expf(-fv));
        float gt = tanhf(gv);
        float os = 1.0f / (1.0f + expf(-ov));
        int idx = b * HID + m0 + m;
        float cn = fs * cst[idx] + is * gt;
        cst[idx] = cn;
        hnext[idx] = os * tanhf(cn);
    }
    __syncthreads();   // protect gsh/smem reuse by the next step in this iter
}

// Persistent kernel: init + full 512-step, 2-layer recurrence.
// One grid barrier per timestep: L0(0); B; loop t: { L1(t); L0(t+1); B }.
__global__ void __launch_bounds__(512, 1)
lstm_persistent_kernel(const float* __restrict__ x,
                       const float* __restrict__ Wih0, const float* __restrict__ Whh0,
                       const float* __restrict__ bih0, const float* __restrict__ bhh0,
                       const float* __restrict__ Wih1, const float* __restrict__ Whh1,
                       const float* __restrict__ bih1, const float* __restrict__ bhh1)
{
    __shared__ __align__(16) float sa[NG][32][64];   // 32 KB
    __shared__ __align__(16) float sw[NG][32][32];   // 16 KB  (total 48 KB)

    // zero my slice of all state buffers (512 elems each per CTA)
    {
        int base = blockIdx.x * 512;
        for (int i = threadIdx.x; i < 512; i += 512) {
            g_h0[0][base + i] = 0.0f; g_h0[1][base + i] = 0.0f;
            g_h1[0][base + i] = 0.0f; g_h1[1][base + i] = 0.0f;
            g_c0[base + i] = 0.0f;    g_c1[base + i] = 0.0f;
        }
    }
    grid_barrier();

    // L0 step t=0
    lstm_step<128>(x, TLEN * 128, g_h0[0], Wih0, Whh0, bih0, bhh0,
                   g_c0, g_h0[1], sa, sw);
    grid_barrier();

    for (int t = 0; t < TLEN; t++) {
        const float* h0cur = g_h0[(t + 1) & 1];          // h0(t)
        lstm_step<1024>(h0cur, HID, g_h1[t & 1], Wih1, Whh1, bih1, bhh1,
                        g_c1, g_h1[(t + 1) & 1], sa, sw);
        if (t + 1 < TLEN) {
            lstm_step<128>(x + (t + 1) * 128, TLEN * 128, h0cur,
                           Wih0, Whh0, bih0, bhh0, g_c0, g_h0[t & 1], sa, sw);
        }
        grid_barrier();
    }
    // final h1(T-1) lives in g_h1[0]
}

__global__ void lstm_fc_kernel(const float* __restrict__ h,
                               const float* __restrict__ w,
                               const float* __restrict__ bias,
                               float* __restrict__ out) {
    __shared__ float warpsum[8];
    int b = blockIdx.x, tid = threadIdx.x;
    float s = 0.0f;
    for (int m = tid; m < HID; m += 256) s += h[b * HID + m] * w[m];
#pragma unroll
    for (int o = 16; o; o >>= 1) s += __shfl_down_sync(0xffffffffu, s, o);
    if ((tid & 31) == 0) warpsum[tid >> 5] = s;
    __syncthreads();
    if (tid == 0) {
        float t = 0.0f;
#pragma unroll
        for (int i = 0; i < 8; i++) t += warpsum[i];
        out[b] = t + bias[0];
    }
}

// ncu steering: with 4 launches per kernel_launch call, the persistent
// kernel is global launch #6, which is what "-s 5 -c 1" profiles.
__global__ void ncu_marker_a() {}
__global__ void ncu_marker_b() {}

extern "C" void kernel_launch(void* const* d_in, const int* in_sizes, int n_in,
                              void* d_out, int out_size) {
    const float* x    = (const float*)d_in[0];
    const float* Wih0 = (const float*)d_in[1];
    const float* Whh0 = (const float*)d_in[2];
    const float* bih0 = (const float*)d_in[3];
    const float* bhh0 = (const float*)d_in[4];
    const float* Wih1 = (const float*)d_in[5];
    const float* Whh1 = (const float*)d_in[6];
    const float* bih1 = (const float*)d_in[7];
    const float* bhh1 = (const float*)d_in[8];
    const float* fcw  = (const float*)d_in[9];
    const float* fcb  = (const float*)d_in[10];
    float* out = (float*)d_out;

    float* h1;
    cudaGetSymbolAddress((void**)&h1, g_h1);   // final h in first buffer

    ncu_marker_a<<<1, 32>>>();
    lstm_persistent_kernel<<<NCTA, 512>>>(x, Wih0, Whh0, bih0, bhh0,
                                          Wih1, Whh1, bih1, bhh1);
    lstm_fc_kernel<<<64, 256>>>(h1, fcw, fcb, out);
    ncu_marker_b<<<1, 32>>>();
}